// round 5
// baseline (speedup 1.0000x reference)
#include <cuda_runtime.h>
#include <cuda_bf16.h>

#define NN   13824
#define BB   256
#define DIM  512
#define OD   1000
#define ODP  1024
#define SK   12
#define KC   (NN / SK)         // 1152
#define CUBE 24

// ---- stencil smem geometry ----
#define YS   432
#define ZS   (10 * YS)
#define HALO_F (4 * ZS)        // 17280
#define WROW 676
#define WSH_F (16 * WROW)      // 10816
#define STEP_SMEM ((HALO_F + WSH_F) * 4)   // 112384 B -> 2 CTA/SM

// ---- GEMM smem geometry (bf16 units) ----
#define AS_STRIDE 72
#define BS_STRIDE 136
#define AS_PLANE  (128 * AS_STRIDE)   // 9216
#define BS_PLANE  (64 * BS_STRIDE)    // 8704
#define BS_OFF    (2 * AS_PLANE)      // 18432
#define STG_UNITS (2 * AS_PLANE + 2 * BS_PLANE)  // 35840 units
#define STG_BYTES (STG_UNITS * 2)                // 71680
#define GEMM_SMEM (2 * STG_BYTES)                // 143360 B

// ---------------- device scratch ----------------
__device__ float g_xp[NN * BB];
__device__ float g_h[2][NN * BB];
__device__ float g_part[SK * BB * ODP];
__device__ __nv_bfloat16 g_WinH[NN * DIM], g_WinL[NN * DIM];
__device__ __nv_bfloat16 g_xTH[DIM * BB],  g_xTL[DIM * BB];
__device__ __nv_bfloat16 g_WoH[OD * NN],   g_WoL[OD * NN];
__device__ __nv_bfloat16 g_hH[NN * BB],    g_hL[NN * BB];

__device__ __forceinline__ float tanh_acc(float x) {
    x = fminf(15.0f, fmaxf(-15.0f, x));
    float e = __expf(2.0f * x);
    return __fdividef(e - 1.0f, e + 1.0f);
}

// ---------------- split conversion (vectorized) ----------------
__global__ __launch_bounds__(256) void split_kernel(const float* __restrict__ s,
                                                    __nv_bfloat16* __restrict__ hi,
                                                    __nv_bfloat16* __restrict__ lo, int n4) {
    int i = blockIdx.x * 256 + threadIdx.x;
    if (i >= n4) return;
    float4 v = *(const float4*)(s + i * 4);
    __nv_bfloat16 h0 = __float2bfloat16_rn(v.x), h1 = __float2bfloat16_rn(v.y);
    __nv_bfloat16 h2 = __float2bfloat16_rn(v.z), h3 = __float2bfloat16_rn(v.w);
    __nv_bfloat162 H0 = {h0, h1}, H1 = {h2, h3};
    *(__nv_bfloat162*)(hi + i * 4) = H0;
    *(__nv_bfloat162*)(hi + i * 4 + 2) = H1;
    __nv_bfloat162 L0 = {__float2bfloat16_rn(v.x - __bfloat162float(h0)),
                         __float2bfloat16_rn(v.y - __bfloat162float(h1))};
    __nv_bfloat162 L1 = {__float2bfloat16_rn(v.z - __bfloat162float(h2)),
                         __float2bfloat16_rn(v.w - __bfloat162float(h3))};
    *(__nv_bfloat162*)(lo + i * 4) = L0;
    *(__nv_bfloat162*)(lo + i * 4 + 2) = L1;
}

__global__ __launch_bounds__(256) void split_xT_kernel(const float* __restrict__ x) {
    int i = blockIdx.x * 256 + threadIdx.x;
    if (i >= DIM * BB) return;
    int k = i / BB, b = i % BB;
    float v = x[b * DIM + k];
    __nv_bfloat16 h = __float2bfloat16_rn(v);
    g_xTH[i] = h;
    g_xTL[i] = __float2bfloat16_rn(v - __bfloat162float(h));
}

// ---------------- mma helpers ----------------
__device__ __forceinline__ void ldsm4(unsigned* r, unsigned addr) {
    asm volatile("ldmatrix.sync.aligned.m8n8.x4.shared.b16 {%0,%1,%2,%3},[%4];"
                 : "=r"(r[0]), "=r"(r[1]), "=r"(r[2]), "=r"(r[3]) : "r"(addr));
}
__device__ __forceinline__ void ldsm4t(unsigned* r, unsigned addr) {
    asm volatile("ldmatrix.sync.aligned.m8n8.x4.trans.shared.b16 {%0,%1,%2,%3},[%4];"
                 : "=r"(r[0]), "=r"(r[1]), "=r"(r[2]), "=r"(r[3]) : "r"(addr));
}
__device__ __forceinline__ void mma_bf16(float* c, const unsigned* a, const unsigned* b) {
    asm volatile("mma.sync.aligned.m16n8k16.row.col.f32.bf16.bf16.f32 "
                 "{%0,%1,%2,%3},{%4,%5,%6,%7},{%8,%9},{%0,%1,%2,%3};"
                 : "+f"(c[0]), "+f"(c[1]), "+f"(c[2]), "+f"(c[3])
                 : "r"(a[0]), "r"(a[1]), "r"(a[2]), "r"(a[3]), "r"(b[0]), "r"(b[1]));
}
__device__ __forceinline__ void cpa16(unsigned s, const void* g, int zs) {
    asm volatile("cp.async.ca.shared.global [%0],[%1],16,%2;" :: "r"(s), "l"(g), "r"(zs));
}
__device__ __forceinline__ void cpa_commit() {
    asm volatile("cp.async.commit_group;" ::: "memory");
}
__device__ __forceinline__ void cpa_wait1() {
    asm volatile("cp.async.wait_group 1;" ::: "memory");
}
__device__ __forceinline__ void cpa_wait0() {
    asm volatile("cp.async.wait_group 0;" ::: "memory");
}

// ---------------- split-precision bf16 MMA GEMM, 2-stage pipeline ----------------
template<int MODE>
__global__ __launch_bounds__(256) void mma_gemm(
    const __nv_bfloat16* __restrict__ Ah, const __nv_bfloat16* __restrict__ Al,
    const __nv_bfloat16* __restrict__ Bh, const __nv_bfloat16* __restrict__ Bl,
    const float* __restrict__ bias, int lda, int kstages)
{
    extern __shared__ __nv_bfloat16 smem[];
    unsigned sbase = (unsigned)__cvta_generic_to_shared(smem);

    int tid = threadIdx.x;
    int m0 = blockIdx.x * 128, n0 = blockIdx.y * 128;
    int kbase = blockIdx.z * kstages * 64;
    int warp = tid >> 5, lane = tid & 31;
    int wm = warp >> 1, wn = warp & 1;

    float acc[2][8][4];
#pragma unroll
    for (int i = 0; i < 2; i++)
#pragma unroll
        for (int j = 0; j < 8; j++)
#pragma unroll
            for (int t = 0; t < 4; t++) acc[i][j][t] = 0.f;

    int ar = tid >> 1, acu = (tid & 1) * 4;
    int br = tid >> 2, bcu = (tid & 3) * 4;
    int okA = (MODE == 0) || (m0 + ar < OD);
    int zsA = okA ? 16 : 0;
    unsigned sA0 = sbase + 2u * (unsigned)(ar * AS_STRIDE + acu * 8);
    unsigned sB0 = sbase + 2u * (unsigned)(BS_OFF + br * BS_STRIDE + bcu * 8);

    int lrow = ((lane >> 3) & 1) * 8 + (lane & 7);
    int lcol = (lane >> 4) * 8;

    const __nv_bfloat16* gAh0 = Ah + (size_t)(m0 + ar) * lda + acu * 8;
    const __nv_bfloat16* gAl0 = Al + (size_t)(m0 + ar) * lda + acu * 8;
    const __nv_bfloat16* gBh0 = Bh + (size_t)br * BB + n0 + bcu * 8;
    const __nv_bfloat16* gBl0 = Bl + (size_t)br * BB + n0 + bcu * 8;

    auto issue = [&](int st) {
        int kg = kbase + st * 64;
        unsigned off = (st & 1) * (unsigned)STG_BYTES;
        const __nv_bfloat16* gAh = gAh0 + kg;
        const __nv_bfloat16* gAl = gAl0 + kg;
        const __nv_bfloat16* gBh = gBh0 + (size_t)kg * BB;
        const __nv_bfloat16* gBl = gBl0 + (size_t)kg * BB;
#pragma unroll
        for (int j = 0; j < 4; j++) {
            cpa16(sA0 + off + j * 16, gAh + j * 8, zsA);
            cpa16(sA0 + off + 2 * AS_PLANE + j * 16, gAl + j * 8, zsA);
            cpa16(sB0 + off + j * 16, gBh + j * 8, 16);
            cpa16(sB0 + off + 2 * BS_PLANE + j * 16, gBl + j * 8, 16);
        }
        cpa_commit();
    };

    issue(0);
    for (int st = 0; st < kstages; st++) {
        if (st + 1 < kstages) issue(st + 1);
        if (st + 1 < kstages) cpa_wait1(); else cpa_wait0();
        __syncthreads();
        unsigned off = (st & 1) * (unsigned)STG_BYTES;

#pragma unroll
        for (int ks = 0; ks < 4; ks++) {
            int ks16 = ks * 16;
            unsigned a_h[2][4], a_l[2][4];
#pragma unroll
            for (int mt = 0; mt < 2; mt++) {
                unsigned aaddr = sbase + off +
                    2u * (unsigned)((wm * 32 + mt * 16 + lrow) * AS_STRIDE + ks16 + lcol);
                ldsm4(a_h[mt], aaddr);
                ldsm4(a_l[mt], aaddr + 2 * AS_PLANE);
            }
#pragma unroll
            for (int np = 0; np < 4; np++) {
                unsigned b_h[4], b_l[4];
                unsigned baddr = sbase + off +
                    2u * (unsigned)(BS_OFF + (ks16 + lrow) * BS_STRIDE + wn * 64 + np * 16 + lcol);
                ldsm4t(b_h, baddr);
                ldsm4t(b_l, baddr + 2 * BS_PLANE);
#pragma unroll
                for (int mt = 0; mt < 2; mt++) {
                    mma_bf16(acc[mt][np * 2],     a_h[mt], b_h);
                    mma_bf16(acc[mt][np * 2],     a_l[mt], b_h);
                    mma_bf16(acc[mt][np * 2],     a_h[mt], b_l);
                    mma_bf16(acc[mt][np * 2 + 1], a_h[mt], b_h + 2);
                    mma_bf16(acc[mt][np * 2 + 1], a_l[mt], b_h + 2);
                    mma_bf16(acc[mt][np * 2 + 1], a_h[mt], b_l + 2);
                }
            }
        }
        __syncthreads();
    }

    int g = lane >> 2, ti = lane & 3;
#pragma unroll
    for (int mt = 0; mt < 2; mt++) {
#pragma unroll
        for (int nt = 0; nt < 8; nt++) {
            float* c = acc[mt][nt];
            int row = m0 + wm * 32 + mt * 16 + g;
            int col = n0 + wn * 64 + nt * 8 + 2 * ti;
            if (MODE == 0) {
                float bv0 = bias[row], bv1 = bias[row + 8];
                *(float2*)(g_xp + (size_t)row * BB + col) = make_float2(c[0] + bv0, c[1] + bv0);
                *(float2*)(g_xp + (size_t)(row + 8) * BB + col) = make_float2(c[2] + bv1, c[3] + bv1);
            } else {
                float* base = g_part + (size_t)(blockIdx.z * BB) * ODP;
                base[(size_t)col * ODP + row] = c[0];
                base[(size_t)(col + 1) * ODP + row] = c[1];
                base[(size_t)col * ODP + row + 8] = c[2];
                base[(size_t)(col + 1) * ODP + row + 8] = c[3];
            }
        }
    }
}

// ---------------- step0: h = tanh(x_proj) ----------------
__global__ __launch_bounds__(256) void step0_kernel() {
    int i = blockIdx.x * 256 + threadIdx.x;
    g_h[0][i] = tanh_acc(g_xp[i]);
}

// ---------------- stencil step: float2 batch, 3-buffer rotation ----------------
__device__ __forceinline__ void stencil_x2(
    int x,
    const float2 (&P0)[9], const float2 (&P1)[9], float2 (&P2)[9],
    const float* sh, const int (&roff)[9], const float* wq,
    const float* xprow, float* horow, int xi)
{
    float wv[28];
#pragma unroll
    for (int t = 0; t < 7; t++)
        *(float4*)(wv + t * 4) = *(const float4*)(wq + x * 28 + t * 4);
#pragma unroll
    for (int r = 0; r < 9; r++)
        P2[r] = *(const float2*)(sh + roff[r] + (x + 2) * 16);

    float2 s0 = make_float2(0.f, 0.f);
    float2 s1 = make_float2(0.f, 0.f);
    float2 s2 = make_float2(0.f, 0.f);
#pragma unroll
    for (int r = 0; r < 9; r++) {
        float w0 = wv[r * 3 + 0], w1 = wv[r * 3 + 1], w2 = wv[r * 3 + 2];
        s0.x = fmaf(w0, P0[r].x, s0.x); s0.y = fmaf(w0, P0[r].y, s0.y);
        s1.x = fmaf(w1, P1[r].x, s1.x); s1.y = fmaf(w1, P1[r].y, s1.y);
        s2.x = fmaf(w2, P2[r].x, s2.x); s2.y = fmaf(w2, P2[r].y, s2.y);
    }
    float2 xp = *(const float2*)(xprow + xi * BB);
    float2 o;
    o.x = tanh_acc(xp.x + s0.x + (s1.x + s2.x));
    o.y = tanh_acc(xp.y + s0.y + (s1.y + s2.y));
    *(float2*)(horow + xi * BB) = o;
}

__global__ __launch_bounds__(256, 2) void step_kernel(int src, const float* __restrict__ Wl) {
    const float* __restrict__ hin = g_h[src];
    float* __restrict__ hout = g_h[src ^ 1];

    extern __shared__ float dyn[];
    float* sh  = dyn;
    float* wsh = dyn + HALO_F;

    int tid = threadIdx.x;
    int y0 = blockIdx.x * 8;
    int z0 = blockIdx.y * 2;
    int b0 = blockIdx.z * 16;

    for (int i = tid; i < 4160; i += 256) {
        int q = i & 3; int site = i >> 2;
        int xx = site % 26; int t2 = site / 26;
        int yy = t2 % 10;   int zz = t2 / 10;
        int gx = xx - 1, gy = y0 + yy - 1, gz = z0 + zz - 1;
        float4 v = make_float4(0.f, 0.f, 0.f, 0.f);
        if ((unsigned)gx < (unsigned)CUBE && (unsigned)gy < (unsigned)CUBE &&
            (unsigned)gz < (unsigned)CUBE)
            v = *(const float4*)(hin + (gz * 576 + gy * 24 + gx) * BB + b0 + q * 4);
        *(float4*)(sh + zz * ZS + yy * YS + xx * 16 + q * 4) = v;
    }
    for (int i = tid; i < 16 * 648; i += 256) {
        int r = i / 648, j = i % 648;
        int x = j / 27, k = j % 27;
        int nr = (z0 + (r >> 3)) * 576 + (y0 + (r & 7)) * 24;
        wsh[r * WROW + x * 28 + k] = Wl[(nr + x) * 27 + k];
    }
    __syncthreads();

    int q  = tid & 7;           // float2 slot: batch offset q*2
    int ry = (tid >> 3) & 7;
    int rz = (tid >> 6) & 1;
    int xq = tid >> 7;          // 0..1
    int x0 = xq * 12;

    int roff[9];
#pragma unroll
    for (int dz = 0; dz < 3; dz++)
#pragma unroll
        for (int dy = 0; dy < 3; dy++)
            roff[dz * 3 + dy] = (rz + dz) * ZS + (ry + dy) * YS + q * 2;

    float2 A[9], B[9], C[9];
#pragma unroll
    for (int r = 0; r < 9; r++) {
        A[r] = *(const float2*)(sh + roff[r] + x0 * 16);
        B[r] = *(const float2*)(sh + roff[r] + (x0 + 1) * 16);
    }

    int nrow = (z0 + rz) * 576 + (y0 + ry) * 24;
    const float* wq = wsh + (rz * 8 + ry) * WROW;
    const float* xprow = g_xp + (size_t)(nrow + x0) * BB + b0 + q * 2;
    float* horow = hout + (size_t)(nrow + x0) * BB + b0 + q * 2;

    stencil_x2(x0 + 0,  A, B, C, sh, roff, wq, xprow, horow, 0);
    stencil_x2(x0 + 1,  B, C, A, sh, roff, wq, xprow, horow, 1);
    stencil_x2(x0 + 2,  C, A, B, sh, roff, wq, xprow, horow, 2);
    stencil_x2(x0 + 3,  A, B, C, sh, roff, wq, xprow, horow, 3);
    stencil_x2(x0 + 4,  B, C, A, sh, roff, wq, xprow, horow, 4);
    stencil_x2(x0 + 5,  C, A, B, sh, roff, wq, xprow, horow, 5);
    stencil_x2(x0 + 6,  A, B, C, sh, roff, wq, xprow, horow, 6);
    stencil_x2(x0 + 7,  B, C, A, sh, roff, wq, xprow, horow, 7);
    stencil_x2(x0 + 8,  C, A, B, sh, roff, wq, xprow, horow, 8);
    stencil_x2(x0 + 9,  A, B, C, sh, roff, wq, xprow, horow, 9);
    stencil_x2(x0 + 10, B, C, A, sh, roff, wq, xprow, horow, 10);
    stencil_x2(x0 + 11, C, A, B, sh, roff, wq, xprow, horow, 11);
}

// ---------------- split h ----------------
__global__ __launch_bounds__(256) void split_h_kernel() {
    int i = blockIdx.x * 256 + threadIdx.x;
    float v = g_h[1][i];
    __nv_bfloat16 h = __float2bfloat16_rn(v);
    g_hH[i] = h;
    g_hL[i] = __float2bfloat16_rn(v - __bfloat162float(h));
}

// ---------------- reduce partials + bias ----------------
__global__ __launch_bounds__(256) void reduce_kernel(const float* __restrict__ bo,
                                                     float* __restrict__ out) {
    int idx = blockIdx.x * 256 + threadIdx.x;
    if (idx >= BB * OD) return;
    int b = idx / OD, o = idx % OD;
    float s = bo[o];
#pragma unroll
    for (int sk = 0; sk < SK; sk++)
        s += g_part[(size_t)(sk * BB + b) * ODP + o];
    out[b * OD + o] = s;
}

// ---------------- launch ----------------
extern "C" void kernel_launch(void* const* d_in, const int* in_sizes, int n_in,
                              void* d_out, int out_size) {
    const float* x   = (const float*)d_in[0];
    const float* Wi  = (const float*)d_in[1];
    const float* bi  = (const float*)d_in[2];
    const float* Wl  = (const float*)d_in[3];
    const float* Wo  = (const float*)d_in[4];
    const float* bo  = (const float*)d_in[5];
    float* out = (float*)d_out;

    cudaFuncSetAttribute(step_kernel, cudaFuncAttributeMaxDynamicSharedMemorySize, STEP_SMEM);
    cudaFuncSetAttribute(mma_gemm<0>, cudaFuncAttributeMaxDynamicSharedMemorySize, GEMM_SMEM);
    cudaFuncSetAttribute(mma_gemm<1>, cudaFuncAttributeMaxDynamicSharedMemorySize, GEMM_SMEM);

    __nv_bfloat16 *winH, *winL, *woH, *woL, *xtH, *xtL, *hH, *hL;
    cudaGetSymbolAddress((void**)&winH, g_WinH);
    cudaGetSymbolAddress((void**)&winL, g_WinL);
    cudaGetSymbolAddress((void**)&woH, g_WoH);
    cudaGetSymbolAddress((void**)&woL, g_WoL);
    cudaGetSymbolAddress((void**)&xtH, g_xTH);
    cudaGetSymbolAddress((void**)&xtL, g_xTL);
    cudaGetSymbolAddress((void**)&hH, g_hH);
    cudaGetSymbolAddress((void**)&hL, g_hL);

    split_kernel<<<(NN * DIM / 4 + 255) / 256, 256>>>(Wi, winH, winL, NN * DIM / 4);
    split_xT_kernel<<<(DIM * BB + 255) / 256, 256>>>(x);
    split_kernel<<<(OD * NN / 4 + 255) / 256, 256>>>(Wo, woH, woL, OD * NN / 4);

    mma_gemm<0><<<dim3(NN / 128, BB / 128, 1), 256, GEMM_SMEM>>>(
        winH, winL, xtH, xtL, bi, DIM, DIM / 64);

    step0_kernel<<<NN * BB / 256, 256>>>();

    int src = 0;
    for (int s = 0; s < 29; s++) {
        step_kernel<<<dim3(CUBE / 8, CUBE / 2, BB / 16), 256, STEP_SMEM>>>(src, Wl);
        src ^= 1;
    }

    split_h_kernel<<<NN * BB / 256, 256>>>();

    mma_gemm<1><<<dim3(ODP / 128, BB / 128, SK), 256, GEMM_SMEM>>>(
        woH, woL, hH, hL, nullptr, NN, KC / 64);
    reduce_kernel<<<(BB * OD + 255) / 256, 256>>>(bo, out);
}

// round 6
// speedup vs baseline: 1.0262x; 1.0262x over previous
#include <cuda_runtime.h>
#include <cuda_bf16.h>

#define NN   13824
#define BB   256
#define DIM  512
#define OD   1000
#define ODP  1024
#define SK   9
#define KC   (NN / SK)         // 1536
#define CUBE 24

// ---- stencil smem geometry ----
#define YS   432
#define ZS   (10 * YS)
#define HALO_F (4 * ZS)        // 17280
#define WROW 676
#define WSH_F (16 * WROW)      // 10816
#define STEP_SMEM ((HALO_F + WSH_F) * 4)   // 112384 B -> 2 CTA/SM

// ---- GEMM smem geometry (bf16 units) ----
#define AS_STRIDE 72
#define BS_STRIDE 136
#define AS_PLANE  (128 * AS_STRIDE)
#define BS_PLANE  (64 * BS_STRIDE)
#define BS_OFF    (2 * AS_PLANE)
#define STG_UNITS (2 * AS_PLANE + 2 * BS_PLANE)
#define STG_BYTES (STG_UNITS * 2)
#define GEMM_SMEM (2 * STG_BYTES)

// ---------------- device scratch ----------------
__device__ float g_xp[NN * BB];
__device__ float g_h[2][NN * BB];
__device__ float g_part[SK * BB * ODP];
__device__ __nv_bfloat16 g_WinH[NN * DIM], g_WinL[NN * DIM];
__device__ __nv_bfloat16 g_xTH[DIM * BB],  g_xTL[DIM * BB];
__device__ __nv_bfloat16 g_WoH[OD * NN],   g_WoL[OD * NN];
__device__ __nv_bfloat16 g_hH[NN * BB],    g_hL[NN * BB];

__device__ __forceinline__ float tanh_acc(float x) {
    x = fminf(15.0f, fmaxf(-15.0f, x));
    float e = __expf(2.0f * x);
    return __fdividef(e - 1.0f, e + 1.0f);
}

// ---------------- split conversion ----------------
__global__ __launch_bounds__(256) void split_kernel(const float* __restrict__ s,
                                                    __nv_bfloat16* __restrict__ hi,
                                                    __nv_bfloat16* __restrict__ lo, int n4) {
    int i = blockIdx.x * 256 + threadIdx.x;
    if (i >= n4) return;
    float4 v = *(const float4*)(s + i * 4);
    __nv_bfloat16 h0 = __float2bfloat16_rn(v.x), h1 = __float2bfloat16_rn(v.y);
    __nv_bfloat16 h2 = __float2bfloat16_rn(v.z), h3 = __float2bfloat16_rn(v.w);
    __nv_bfloat162 H0 = {h0, h1}, H1 = {h2, h3};
    *(__nv_bfloat162*)(hi + i * 4) = H0;
    *(__nv_bfloat162*)(hi + i * 4 + 2) = H1;
    __nv_bfloat162 L0 = {__float2bfloat16_rn(v.x - __bfloat162float(h0)),
                         __float2bfloat16_rn(v.y - __bfloat162float(h1))};
    __nv_bfloat162 L1 = {__float2bfloat16_rn(v.z - __bfloat162float(h2)),
                         __float2bfloat16_rn(v.w - __bfloat162float(h3))};
    *(__nv_bfloat162*)(lo + i * 4) = L0;
    *(__nv_bfloat162*)(lo + i * 4 + 2) = L1;
}

// transpose x[b][k] -> xT[k][b] with split, smem tiled
__global__ __launch_bounds__(256) void split_xT_kernel(const float* __restrict__ x) {
    __shared__ float t[32][33];
    int bx = blockIdx.x * 32, kx = blockIdx.y * 32;
    int tx = threadIdx.x & 31, ty = threadIdx.x >> 5;   // 32 x 8
#pragma unroll
    for (int j = ty; j < 32; j += 8)
        t[j][tx] = x[(size_t)(bx + j) * DIM + kx + tx];
    __syncthreads();
#pragma unroll
    for (int j = ty; j < 32; j += 8) {
        float v = t[tx][j];
        __nv_bfloat16 h = __float2bfloat16_rn(v);
        size_t o = (size_t)(kx + j) * BB + bx + tx;
        g_xTH[o] = h;
        g_xTL[o] = __float2bfloat16_rn(v - __bfloat162float(h));
    }
}

// ---------------- mma helpers ----------------
__device__ __forceinline__ void ldsm4(unsigned* r, unsigned addr) {
    asm volatile("ldmatrix.sync.aligned.m8n8.x4.shared.b16 {%0,%1,%2,%3},[%4];"
                 : "=r"(r[0]), "=r"(r[1]), "=r"(r[2]), "=r"(r[3]) : "r"(addr));
}
__device__ __forceinline__ void ldsm4t(unsigned* r, unsigned addr) {
    asm volatile("ldmatrix.sync.aligned.m8n8.x4.trans.shared.b16 {%0,%1,%2,%3},[%4];"
                 : "=r"(r[0]), "=r"(r[1]), "=r"(r[2]), "=r"(r[3]) : "r"(addr));
}
__device__ __forceinline__ void mma_bf16(float* c, const unsigned* a, const unsigned* b) {
    asm volatile("mma.sync.aligned.m16n8k16.row.col.f32.bf16.bf16.f32 "
                 "{%0,%1,%2,%3},{%4,%5,%6,%7},{%8,%9},{%0,%1,%2,%3};"
                 : "+f"(c[0]), "+f"(c[1]), "+f"(c[2]), "+f"(c[3])
                 : "r"(a[0]), "r"(a[1]), "r"(a[2]), "r"(a[3]), "r"(b[0]), "r"(b[1]));
}
__device__ __forceinline__ void cpa16(unsigned s, const void* g, int zs) {
    asm volatile("cp.async.ca.shared.global [%0],[%1],16,%2;" :: "r"(s), "l"(g), "r"(zs));
}
__device__ __forceinline__ void cpa_commit() {
    asm volatile("cp.async.commit_group;" ::: "memory");
}
__device__ __forceinline__ void cpa_wait1() {
    asm volatile("cp.async.wait_group 1;" ::: "memory");
}
__device__ __forceinline__ void cpa_wait0() {
    asm volatile("cp.async.wait_group 0;" ::: "memory");
}

// ---------------- split-precision bf16 MMA GEMM, 2-stage pipeline ----------------
template<int MODE>
__global__ __launch_bounds__(256) void mma_gemm(
    const __nv_bfloat16* __restrict__ Ah, const __nv_bfloat16* __restrict__ Al,
    const __nv_bfloat16* __restrict__ Bh, const __nv_bfloat16* __restrict__ Bl,
    const float* __restrict__ bias, int lda, int kstages)
{
    extern __shared__ __nv_bfloat16 smem[];
    unsigned sbase = (unsigned)__cvta_generic_to_shared(smem);

    int tid = threadIdx.x;
    int m0 = blockIdx.x * 128, n0 = blockIdx.y * 128;
    int kbase = blockIdx.z * kstages * 64;
    int warp = tid >> 5, lane = tid & 31;
    int wm = warp >> 1, wn = warp & 1;

    float acc[2][8][4];
#pragma unroll
    for (int i = 0; i < 2; i++)
#pragma unroll
        for (int j = 0; j < 8; j++)
#pragma unroll
            for (int t = 0; t < 4; t++) acc[i][j][t] = 0.f;

    int ar = tid >> 1, acu = (tid & 1) * 4;
    int br = tid >> 2, bcu = (tid & 3) * 4;
    int okA = (MODE == 0) || (m0 + ar < OD);
    int zsA = okA ? 16 : 0;
    unsigned sA0 = sbase + 2u * (unsigned)(ar * AS_STRIDE + acu * 8);
    unsigned sB0 = sbase + 2u * (unsigned)(BS_OFF + br * BS_STRIDE + bcu * 8);

    int lrow = ((lane >> 3) & 1) * 8 + (lane & 7);
    int lcol = (lane >> 4) * 8;

    const __nv_bfloat16* gAh0 = Ah + (size_t)(m0 + ar) * lda + acu * 8;
    const __nv_bfloat16* gAl0 = Al + (size_t)(m0 + ar) * lda + acu * 8;
    const __nv_bfloat16* gBh0 = Bh + (size_t)br * BB + n0 + bcu * 8;
    const __nv_bfloat16* gBl0 = Bl + (size_t)br * BB + n0 + bcu * 8;

    auto issue = [&](int st) {
        int kg = kbase + st * 64;
        unsigned off = (st & 1) * (unsigned)STG_BYTES;
        const __nv_bfloat16* gAh = gAh0 + kg;
        const __nv_bfloat16* gAl = gAl0 + kg;
        const __nv_bfloat16* gBh = gBh0 + (size_t)kg * BB;
        const __nv_bfloat16* gBl = gBl0 + (size_t)kg * BB;
#pragma unroll
        for (int j = 0; j < 4; j++) {
            cpa16(sA0 + off + j * 16, gAh + j * 8, zsA);
            cpa16(sA0 + off + 2 * AS_PLANE + j * 16, gAl + j * 8, zsA);
            cpa16(sB0 + off + j * 16, gBh + j * 8, 16);
            cpa16(sB0 + off + 2 * BS_PLANE + j * 16, gBl + j * 8, 16);
        }
        cpa_commit();
    };

    issue(0);
    for (int st = 0; st < kstages; st++) {
        if (st + 1 < kstages) issue(st + 1);
        if (st + 1 < kstages) cpa_wait1(); else cpa_wait0();
        __syncthreads();
        unsigned off = (st & 1) * (unsigned)STG_BYTES;

#pragma unroll
        for (int ks = 0; ks < 4; ks++) {
            int ks16 = ks * 16;
            unsigned a_h[2][4], a_l[2][4];
#pragma unroll
            for (int mt = 0; mt < 2; mt++) {
                unsigned aaddr = sbase + off +
                    2u * (unsigned)((wm * 32 + mt * 16 + lrow) * AS_STRIDE + ks16 + lcol);
                ldsm4(a_h[mt], aaddr);
                ldsm4(a_l[mt], aaddr + 2 * AS_PLANE);
            }
#pragma unroll
            for (int np = 0; np < 4; np++) {
                unsigned b_h[4], b_l[4];
                unsigned baddr = sbase + off +
                    2u * (unsigned)(BS_OFF + (ks16 + lrow) * BS_STRIDE + wn * 64 + np * 16 + lcol);
                ldsm4t(b_h, baddr);
                ldsm4t(b_l, baddr + 2 * BS_PLANE);
#pragma unroll
                for (int mt = 0; mt < 2; mt++) {
                    mma_bf16(acc[mt][np * 2],     a_h[mt], b_h);
                    mma_bf16(acc[mt][np * 2],     a_l[mt], b_h);
                    mma_bf16(acc[mt][np * 2],     a_h[mt], b_l);
                    mma_bf16(acc[mt][np * 2 + 1], a_h[mt], b_h + 2);
                    mma_bf16(acc[mt][np * 2 + 1], a_l[mt], b_h + 2);
                    mma_bf16(acc[mt][np * 2 + 1], a_h[mt], b_l + 2);
                }
            }
        }
        __syncthreads();
    }

    int g = lane >> 2, ti = lane & 3;
#pragma unroll
    for (int mt = 0; mt < 2; mt++) {
#pragma unroll
        for (int nt = 0; nt < 8; nt++) {
            float* c = acc[mt][nt];
            int row = m0 + wm * 32 + mt * 16 + g;
            int col = n0 + wn * 64 + nt * 8 + 2 * ti;
            if (MODE == 0) {
                float bv0 = bias[row], bv1 = bias[row + 8];
                *(float2*)(g_xp + (size_t)row * BB + col) = make_float2(c[0] + bv0, c[1] + bv0);
                *(float2*)(g_xp + (size_t)(row + 8) * BB + col) = make_float2(c[2] + bv1, c[3] + bv1);
            } else {
                float* base = g_part + (size_t)(blockIdx.z * BB) * ODP;
                base[(size_t)col * ODP + row] = c[0];
                base[(size_t)(col + 1) * ODP + row] = c[1];
                base[(size_t)col * ODP + row + 8] = c[2];
                base[(size_t)(col + 1) * ODP + row + 8] = c[3];
            }
        }
    }
}

// ---------------- step0: h = tanh(x_proj) ----------------
__global__ __launch_bounds__(256) void step0_kernel() {
    int i = blockIdx.x * 256 + threadIdx.x;
    g_h[0][i] = tanh_acc(g_xp[i]);
}

// ---------------- stencil step: float2 batch, xp pre-accumulated ----------------
#define STENCIL_X(XI, P0, P1, P2)                                              \
    {                                                                          \
        const int x = x0 + (XI);                                               \
        float wv[28];                                                          \
        _Pragma("unroll")                                                      \
        for (int t = 0; t < 7; t++)                                            \
            *(float4*)(wv + t * 4) = *(const float4*)(wq + x * 28 + t * 4);    \
        _Pragma("unroll")                                                      \
        for (int r = 0; r < 9; r++)                                            \
            P2[r] = *(const float2*)(sh + roff[r] + (x + 2) * 16);             \
        float2 s0 = acc[XI];                                                   \
        float2 s1 = make_float2(0.f, 0.f);                                     \
        float2 s2 = make_float2(0.f, 0.f);                                     \
        _Pragma("unroll")                                                      \
        for (int r = 0; r < 9; r++) {                                          \
            float w0 = wv[r * 3 + 0], w1 = wv[r * 3 + 1], w2 = wv[r * 3 + 2];  \
            s0.x = fmaf(w0, P0[r].x, s0.x); s0.y = fmaf(w0, P0[r].y, s0.y);    \
            s1.x = fmaf(w1, P1[r].x, s1.x); s1.y = fmaf(w1, P1[r].y, s1.y);    \
            s2.x = fmaf(w2, P2[r].x, s2.x); s2.y = fmaf(w2, P2[r].y, s2.y);    \
        }                                                                      \
        float2 o;                                                              \
        o.x = tanh_acc(s0.x + (s1.x + s2.x));                                  \
        o.y = tanh_acc(s0.y + (s1.y + s2.y));                                  \
        *(float2*)(horow + (XI) * BB) = o;                                     \
    }

__global__ __launch_bounds__(256, 2) void step_kernel(int src, const float* __restrict__ Wl) {
    const float* __restrict__ hin = g_h[src];
    float* __restrict__ hout = g_h[src ^ 1];

    extern __shared__ float dyn[];
    float* sh  = dyn;
    float* wsh = dyn + HALO_F;

    int tid = threadIdx.x;
    int y0 = blockIdx.x * 8;
    int z0 = blockIdx.y * 2;
    int b0 = blockIdx.z * 16;

    for (int i = tid; i < 4160; i += 256) {
        int q = i & 3; int site = i >> 2;
        int xx = site % 26; int t2 = site / 26;
        int yy = t2 % 10;   int zz = t2 / 10;
        int gx = xx - 1, gy = y0 + yy - 1, gz = z0 + zz - 1;
        float4 v = make_float4(0.f, 0.f, 0.f, 0.f);
        if ((unsigned)gx < (unsigned)CUBE && (unsigned)gy < (unsigned)CUBE &&
            (unsigned)gz < (unsigned)CUBE)
            v = *(const float4*)(hin + (gz * 576 + gy * 24 + gx) * BB + b0 + q * 4);
        *(float4*)(sh + zz * ZS + yy * YS + xx * 16 + q * 4) = v;
    }
    for (int i = tid; i < 16 * 648; i += 256) {
        int r = i / 648, j = i % 648;
        int x = j / 27, k = j % 27;
        int nr = (z0 + (r >> 3)) * 576 + (y0 + (r & 7)) * 24;
        wsh[r * WROW + x * 28 + k] = Wl[(nr + x) * 27 + k];
    }
    __syncthreads();

    int q  = tid & 7;
    int ry = (tid >> 3) & 7;
    int rz = (tid >> 6) & 1;
    int xq = tid >> 7;
    int x0 = xq * 12;

    int roff[9];
#pragma unroll
    for (int dz = 0; dz < 3; dz++)
#pragma unroll
        for (int dy = 0; dy < 3; dy++)
            roff[dz * 3 + dy] = (rz + dz) * ZS + (ry + dy) * YS + q * 2;

    float2 A[9], B[9], C[9];
#pragma unroll
    for (int r = 0; r < 9; r++) {
        A[r] = *(const float2*)(sh + roff[r] + x0 * 16);
        B[r] = *(const float2*)(sh + roff[r] + (x0 + 1) * 16);
    }

    int nrow = (z0 + rz) * 576 + (y0 + ry) * 24;
    const float* wq = wsh + (rz * 8 + ry) * WROW;
    const float* xprow = g_xp + (size_t)(nrow + x0) * BB + b0 + q * 2;
    float* horow = hout + (size_t)(nrow + x0) * BB + b0 + q * 2;

    // prefetch xp: first half, batched (MLP=6, one latency exposure)
    float2 acc[12];
#pragma unroll
    for (int j = 0; j < 6; j++) acc[j] = *(const float2*)(xprow + j * BB);

    STENCIL_X(0, A, B, C)
    STENCIL_X(1, B, C, A)
    STENCIL_X(2, C, A, B)

    // prefetch xp: second half
#pragma unroll
    for (int j = 6; j < 12; j++) acc[j] = *(const float2*)(xprow + j * BB);

    STENCIL_X(3, A, B, C)
    STENCIL_X(4, B, C, A)
    STENCIL_X(5, C, A, B)
    STENCIL_X(6, A, B, C)
    STENCIL_X(7, B, C, A)
    STENCIL_X(8, C, A, B)
    STENCIL_X(9, A, B, C)
    STENCIL_X(10, B, C, A)
    STENCIL_X(11, C, A, B)
}

// ---------------- split h ----------------
__global__ __launch_bounds__(256) void split_h_kernel() {
    int i = blockIdx.x * 256 + threadIdx.x;
    float v = g_h[1][i];
    __nv_bfloat16 h = __float2bfloat16_rn(v);
    g_hH[i] = h;
    g_hL[i] = __float2bfloat16_rn(v - __bfloat162float(h));
}

// ---------------- reduce partials + bias ----------------
__global__ __launch_bounds__(256) void reduce_kernel(const float* __restrict__ bo,
                                                     float* __restrict__ out) {
    int idx = blockIdx.x * 256 + threadIdx.x;
    if (idx >= BB * OD) return;
    int b = idx / OD, o = idx % OD;
    float s = bo[o];
#pragma unroll
    for (int sk = 0; sk < SK; sk++)
        s += g_part[(size_t)(sk * BB + b) * ODP + o];
    out[b * OD + o] = s;
}

// ---------------- launch ----------------
extern "C" void kernel_launch(void* const* d_in, const int* in_sizes, int n_in,
                              void* d_out, int out_size) {
    const float* x   = (const float*)d_in[0];
    const float* Wi  = (const float*)d_in[1];
    const float* bi  = (const float*)d_in[2];
    const float* Wl  = (const float*)d_in[3];
    const float* Wo  = (const float*)d_in[4];
    const float* bo  = (const float*)d_in[5];
    float* out = (float*)d_out;

    cudaFuncSetAttribute(step_kernel, cudaFuncAttributeMaxDynamicSharedMemorySize, STEP_SMEM);
    cudaFuncSetAttribute(mma_gemm<0>, cudaFuncAttributeMaxDynamicSharedMemorySize, GEMM_SMEM);
    cudaFuncSetAttribute(mma_gemm<1>, cudaFuncAttributeMaxDynamicSharedMemorySize, GEMM_SMEM);

    __nv_bfloat16 *winH, *winL, *woH, *woL, *xtH, *xtL, *hH, *hL;
    cudaGetSymbolAddress((void**)&winH, g_WinH);
    cudaGetSymbolAddress((void**)&winL, g_WinL);
    cudaGetSymbolAddress((void**)&woH, g_WoH);
    cudaGetSymbolAddress((void**)&woL, g_WoL);
    cudaGetSymbolAddress((void**)&xtH, g_xTH);
    cudaGetSymbolAddress((void**)&xtL, g_xTL);
    cudaGetSymbolAddress((void**)&hH, g_hH);
    cudaGetSymbolAddress((void**)&hL, g_hL);

    split_kernel<<<(NN * DIM / 4 + 255) / 256, 256>>>(Wi, winH, winL, NN * DIM / 4);
    split_xT_kernel<<<dim3(BB / 32, DIM / 32), 256>>>(x);
    split_kernel<<<(OD * NN / 4 + 255) / 256, 256>>>(Wo, woH, woL, OD * NN / 4);

    mma_gemm<0><<<dim3(NN / 128, BB / 128, 1), 256, GEMM_SMEM>>>(
        winH, winL, xtH, xtL, bi, DIM, DIM / 64);

    step0_kernel<<<NN * BB / 256, 256>>>();

    int src = 0;
    for (int s = 0; s < 29; s++) {
        step_kernel<<<dim3(CUBE / 8, CUBE / 2, BB / 16), 256, STEP_SMEM>>>(src, Wl);
        src ^= 1;
    }

    split_h_kernel<<<NN * BB / 256, 256>>>();

    mma_gemm<1><<<dim3(ODP / 128, BB / 128, SK), 256, GEMM_SMEM>>>(
        woH, woL, hH, hL, nullptr, NN, KC / 64);
    reduce_kernel<<<(BB * OD + 255) / 256, 256>>>(bo, out);
}